// round 6
// baseline (speedup 1.0000x reference)
#include <cuda_runtime.h>
#include <math.h>

// HawkesPointProcess: B=8, N=4096, split each row across KC CTAs with a
// cross-CTA affine-scan handoff through __device__ scratch + spin flags.
//
//   A_i = e_i*(A_{i-1}+1), e_i = exp(-beta*(t_i - t_{i-1})), e_0 := 0
//   lamb_i = A_i*alpha*beta + mu
//   out[b] = sum_i log(lamb_i+1e-8)*m_i
//            - [ (t1-t0)*mu - alpha*( sum_i exp(-beta*(t1-t_i)*m_i + (1-m_i)*(-1e20)) - sum_i m_i ) ]

#define KC    8      // CTAs per batch row (grid = B*KC = 64, single wave)
#define MAXB  16
#define MAXW  32

// Cross-CTA scratch. Zero-initialized at module load; flags are reset by the
// row aggregator at the end of every run so graph replays start clean.
__device__ volatile float g_G[MAXB][KC];
__device__ volatile float g_Hv[MAXB][KC];
__device__ volatile float g_pl[MAXB][KC];
__device__ volatile float g_pc[MAXB][KC];
__device__ volatile float g_pm[MAXB][KC];
__device__ volatile int   g_f1[MAXB][KC];
__device__ volatile int   g_f2[MAXB][KC];

__device__ __forceinline__ float softplus_fast(float x) {
    // |x| ~ 0.3 here; fast-math version is accurate to ~1e-6 rel.
    return __logf(1.0f + __expf(x));
}

__global__ __launch_bounds__(512, 1)
void hawkes_mc(const float* __restrict__ et,
               const float* __restrict__ mask,
               const float* __restrict__ t0v,
               const float* __restrict__ t1v,
               const float* __restrict__ mu_raw,
               const float* __restrict__ alpha_raw,
               const float* __restrict__ beta_raw,
               float* __restrict__ out,
               int N) {
    const int row  = blockIdx.x / KC;
    const int c    = blockIdx.x % KC;
    const int tid  = threadIdx.x;
    const int lane = tid & 31;
    const int warp = tid >> 5;
    const int T    = blockDim.x;       // 512
    const int nw   = T >> 5;           // 16 warps

    const float mu    = softplus_fast(mu_raw[0]);
    const float alpha = softplus_fast(alpha_raw[0]);
    const float beta  = softplus_fast(beta_raw[0]);
    const float T1    = t1v[row];

    const int idx = c * T + tid;                    // element index within row
    const float* t = et   + (size_t)row * N;
    const float* m = mask + (size_t)row * N;

    const float ti = t[idx];
    const float mi = m[idx];
    const float tp = (idx == 0) ? ti : t[idx - 1];
    float e = (idx == 0) ? 0.0f : __expf(-beta * (ti - tp));

    // ---- block affine scan over (G,H): compose(cur,prev) = (Gc*Gp, Gc*Hp+Hc)
    float G = e, H = e;
    #pragma unroll
    for (int off = 1; off < 32; off <<= 1) {
        float Gp = __shfl_up_sync(0xffffffffu, G, off);
        float Hp = __shfl_up_sync(0xffffffffu, H, off);
        if (lane >= off) { H = fmaf(G, Hp, H); G *= Gp; }
    }
    float Gex = __shfl_up_sync(0xffffffffu, G, 1);   // lane-exclusive
    float Hex = __shfl_up_sync(0xffffffffu, H, 1);
    if (lane == 0) { Gex = 1.0f; Hex = 0.0f; }

    __shared__ float sG[MAXW], sH[MAXW];
    __shared__ float sr[3 * MAXW];
    __shared__ float sAin;

    if (lane == 31) { sG[warp] = G; sH[warp] = H; }
    __syncthreads();
    if (warp == 0) {
        float g = (lane < nw) ? sG[lane] : 1.0f;
        float h = (lane < nw) ? sH[lane] : 0.0f;
        #pragma unroll
        for (int off = 1; off < 32; off <<= 1) {
            float gp = __shfl_up_sync(0xffffffffu, g, off);
            float hp = __shfl_up_sync(0xffffffffu, h, off);
            if (lane >= off) { h = fmaf(g, hp, h); g *= gp; }
        }
        sG[lane] = g;  sH[lane] = h;                 // inclusive warp prefixes
    }
    __syncthreads();

    // ---- publish this CTA's aggregate transform, then look back.
    if (tid == 0) {
        g_G[row][c]  = sG[nw - 1];
        g_Hv[row][c] = sH[nw - 1];
        __threadfence();
        g_f1[row][c] = 1;
    }

    if (warp == 0) {
        float Gj = 1.0f, Hj = 0.0f;
        if (lane < c) {                               // spin on predecessors
            while (g_f1[row][lane] == 0) { }
            __threadfence();
            Gj = g_G[row][lane];
            Hj = g_Hv[row][lane];
        }
        __syncwarp();
        float A = 0.0f;                               // fold in index order
        #pragma unroll
        for (int j = 0; j < KC - 1; j++) {
            float gj = __shfl_sync(0xffffffffu, Gj, j);
            float hj = __shfl_sync(0xffffffffu, Hj, j);
            if (j < c) A = fmaf(gj, A, hj);
        }
        if (lane == 0) sAin = A;
    }
    __syncthreads();
    const float A0 = sAin;

    // ---- per-thread state and pointwise terms.
    const float Gwp = (warp == 0) ? 1.0f : sG[warp - 1];
    const float Hwp = (warp == 0) ? 0.0f : sH[warp - 1];
    const float Aw    = fmaf(Gwp, A0, Hwp);           // state entering this warp
    const float Aprev = fmaf(Gex, Aw, Hex);           // state entering this elem
    const float A     = fmaf(e, Aprev, e);            // A_i = e*(A_{i-1}+1)

    const float ab   = alpha * beta;
    const float lamb = fmaf(A, ab, mu);
    float acc_log  = __logf(lamb + 1e-8f) * mi;
    float acc_comp = __expf(fmaf(-beta * (T1 - ti), mi, (1.0f - mi) * (-1e20f)));
    float acc_m    = mi;

    // ---- block reduce (3 scalars).
    #pragma unroll
    for (int off = 16; off > 0; off >>= 1) {
        acc_log  += __shfl_xor_sync(0xffffffffu, acc_log,  off);
        acc_comp += __shfl_xor_sync(0xffffffffu, acc_comp, off);
        acc_m    += __shfl_xor_sync(0xffffffffu, acc_m,    off);
    }
    if (lane == 0) {
        sr[warp]            = acc_log;
        sr[MAXW + warp]     = acc_comp;
        sr[2 * MAXW + warp] = acc_m;
    }
    __syncthreads();

    if (warp == 0) {
        float v0 = (lane < nw) ? sr[lane]            : 0.0f;
        float v1 = (lane < nw) ? sr[MAXW + lane]     : 0.0f;
        float v2 = (lane < nw) ? sr[2 * MAXW + lane] : 0.0f;
        #pragma unroll
        for (int off = 16; off > 0; off >>= 1) {
            v0 += __shfl_xor_sync(0xffffffffu, v0, off);
            v1 += __shfl_xor_sync(0xffffffffu, v1, off);
            v2 += __shfl_xor_sync(0xffffffffu, v2, off);
        }
        if (lane == 0) {                              // publish partials
            g_pl[row][c] = v0;
            g_pc[row][c] = v1;
            g_pm[row][c] = v2;
            __threadfence();
            g_f2[row][c] = 1;
        }

        // ---- row aggregator: last CTA of the row.
        if (c == KC - 1) {
            float pl = 0.0f, pc = 0.0f, pm = 0.0f;
            if (lane < KC) {
                while (g_f2[row][lane] == 0) { }
                __threadfence();
                pl = g_pl[row][lane];
                pc = g_pc[row][lane];
                pm = g_pm[row][lane];
            }
            __syncwarp();
            #pragma unroll
            for (int off = 16; off > 0; off >>= 1) {
                pl += __shfl_xor_sync(0xffffffffu, pl, off);
                pc += __shfl_xor_sync(0xffffffffu, pc, off);
                pm += __shfl_xor_sync(0xffffffffu, pm, off);
            }
            if (lane == 0) {
                const float T0 = t0v[row];
                const float compensator = (T1 - T0) * mu - alpha * (pc - pm);
                out[row] = pl - compensator;
            }
            // Reset flags for the next graph replay. Safe: every CTA's flag1
            // reads precede its flag2 publish, and we saw all flag2.
            if (lane < KC) { g_f1[row][lane] = 0; g_f2[row][lane] = 0; }
        }
    }
}

extern "C" void kernel_launch(void* const* d_in, const int* in_sizes, int n_in,
                              void* d_out, int out_size) {
    const float* event_times = (const float*)d_in[0];
    const float* input_mask  = (const float*)d_in[1];
    const float* t0          = (const float*)d_in[2];
    const float* t1          = (const float*)d_in[3];
    const float* mu          = (const float*)d_in[4];
    const float* alpha       = (const float*)d_in[5];
    const float* beta        = (const float*)d_in[6];
    float* out = (float*)d_out;

    const int B = in_sizes[2];       // t0 has B elements
    const int N = in_sizes[0] / B;   // 4096
    const int T = N / KC;            // 512 threads per CTA

    hawkes_mc<<<B * KC, T>>>(event_times, input_mask, t0, t1,
                             mu, alpha, beta, out, N);
}

// round 7
// speedup vs baseline: 2.1581x; 2.1581x over previous
#include <cuda_runtime.h>
#include <math.h>

// HawkesPointProcess: B=8, N=4096. One CTA per batch row, 1024 threads,
// 4 elements/thread, shuffle-based affine scan + reductions.
//
//   A_i = e_i*(A_{i-1}+1), e_i = exp(-beta*(t_i - t_{i-1})), e_0 := 0
//   lamb_i = A_i*alpha*beta + mu
//   out[b] = sum_i log(lamb_i+1e-8)*m_i
//            - [ (t1-t0)*mu - alpha*( sum_i exp(-beta*(t1-t_i)*m_i + (1-m_i)*(-1e20)) - sum_i m_i ) ]

#define NT 1024
#define CHUNK 4      // NT*CHUNK == N == 4096

__device__ __forceinline__ float softplus_fast(float x) {
    // |x| ~ 0.3 here; MUFU-based, rel err ~1e-6 — 10 instr vs ~180 for libm.
    return __logf(1.0f + __expf(x));
}

__global__ __launch_bounds__(NT, 1)
void hawkes_kernel(const float* __restrict__ et,
                   const float* __restrict__ mask,
                   const float* __restrict__ t0v,
                   const float* __restrict__ t1v,
                   const float* __restrict__ mu_raw,
                   const float* __restrict__ alpha_raw,
                   const float* __restrict__ beta_raw,
                   float* __restrict__ out,
                   int N) {
    const int b    = blockIdx.x;
    const int tid  = threadIdx.x;
    const int lane = tid & 31;
    const int warp = tid >> 5;

    const float mu    = softplus_fast(mu_raw[0]);
    const float alpha = softplus_fast(alpha_raw[0]);
    const float beta  = softplus_fast(beta_raw[0]);
    const float T0 = t0v[b];
    const float T1 = t1v[b];

    const float* t = et   + (size_t)b * N;
    const float* m = mask + (size_t)b * N;

    __shared__ float sG[32];
    __shared__ float sH[32];
    __shared__ float r0[32], r1[32], r2[32];

    const int base = tid * CHUNK;

    // Coalesced vector loads.
    const float4 t4 = *reinterpret_cast<const float4*>(t + base);
    const float4 m4 = *reinterpret_cast<const float4*>(m + base);
    const float tprev = (tid == 0) ? t4.x : t[base - 1];

    // Per-element decay factors (4 independent MUFU exps, fully overlapped).
    float e0 = __expf(-beta * (t4.x - tprev));
    float e1 = __expf(-beta * (t4.y - t4.x));
    float e2 = __expf(-beta * (t4.z - t4.y));
    float e3 = __expf(-beta * (t4.w - t4.z));
    if (tid == 0) e0 = 0.0f;   // global element 0: A_0 = 0

    // Chunk-local affine transform (A_out = G*A_in + H).
    float H;
    {
        float A = e0;
        A = fmaf(e1, A, e1);
        A = fmaf(e2, A, e2);
        A = fmaf(e3, A, e3);
        H = A;
    }
    float G = (e0 * e1) * (e2 * e3);

    // Inclusive warp scan over (G,H): compose(cur, prev) = (Gc*Gp, Gc*Hp + Hc).
    #pragma unroll
    for (int off = 1; off < 32; off <<= 1) {
        float Gp = __shfl_up_sync(0xffffffffu, G, off);
        float Hp = __shfl_up_sync(0xffffffffu, H, off);
        if (lane >= off) { H = fmaf(G, Hp, H); G *= Gp; }
    }
    // Lane-exclusive transform within warp.
    float Gex = __shfl_up_sync(0xffffffffu, G, 1);
    float Hex = __shfl_up_sync(0xffffffffu, H, 1);
    if (lane == 0) { Gex = 1.0f; Hex = 0.0f; }

    // Warp aggregates -> smem, warp 0 scans them.
    if (lane == 31) { sG[warp] = G; sH[warp] = H; }
    __syncthreads();
    if (warp == 0) {
        float g = sG[lane], h = sH[lane];
        #pragma unroll
        for (int off = 1; off < 32; off <<= 1) {
            float gp = __shfl_up_sync(0xffffffffu, g, off);
            float hp = __shfl_up_sync(0xffffffffu, h, off);
            if (lane >= off) { h = fmaf(g, hp, h); g *= gp; }
        }
        sH[lane] = h;   // inclusive warp-prefix values (applied to A=0)
    }
    __syncthreads();

    // Incoming state for this thread's chunk.
    const float Aw   = (warp == 0) ? 0.0f : sH[warp - 1];
    const float A_in = fmaf(Gex, Aw, Hex);

    // Phase 2: replay with true incoming state (e_k cached in registers).
    const float ab = alpha * beta;
    float acc_log, acc_comp, acc_m;
    {
        float A = A_in;
        A = fmaf(e0, A, e0);
        float l0 = __logf(fmaf(A, ab, mu) + 1e-8f);
        A = fmaf(e1, A, e1);
        float l1 = __logf(fmaf(A, ab, mu) + 1e-8f);
        A = fmaf(e2, A, e2);
        float l2 = __logf(fmaf(A, ab, mu) + 1e-8f);
        A = fmaf(e3, A, e3);
        float l3 = __logf(fmaf(A, ab, mu) + 1e-8f);
        acc_log = l0 * m4.x + l1 * m4.y + l2 * m4.z + l3 * m4.w;

        // Compensator kernel terms (exact reference formula incl. mask).
        float k0 = __expf(fmaf(-beta * (T1 - t4.x), m4.x, (1.0f - m4.x) * (-1e20f)));
        float k1 = __expf(fmaf(-beta * (T1 - t4.y), m4.y, (1.0f - m4.y) * (-1e20f)));
        float k2 = __expf(fmaf(-beta * (T1 - t4.z), m4.z, (1.0f - m4.z) * (-1e20f)));
        float k3 = __expf(fmaf(-beta * (T1 - t4.w), m4.w, (1.0f - m4.w) * (-1e20f)));
        acc_comp = (k0 + k1) + (k2 + k3);
        acc_m    = (m4.x + m4.y) + (m4.z + m4.w);
    }

    // Warp reductions (3 scalars, shuffle only).
    #pragma unroll
    for (int off = 16; off > 0; off >>= 1) {
        acc_log  += __shfl_xor_sync(0xffffffffu, acc_log,  off);
        acc_comp += __shfl_xor_sync(0xffffffffu, acc_comp, off);
        acc_m    += __shfl_xor_sync(0xffffffffu, acc_m,    off);
    }
    if (lane == 0) { r0[warp] = acc_log; r1[warp] = acc_comp; r2[warp] = acc_m; }
    __syncthreads();

    if (warp == 0) {
        float v0 = r0[lane], v1 = r1[lane], v2 = r2[lane];
        #pragma unroll
        for (int off = 16; off > 0; off >>= 1) {
            v0 += __shfl_xor_sync(0xffffffffu, v0, off);
            v1 += __shfl_xor_sync(0xffffffffu, v1, off);
            v2 += __shfl_xor_sync(0xffffffffu, v2, off);
        }
        if (lane == 0) {
            float compensator = (T1 - T0) * mu - alpha * (v1 - v2);
            out[b] = v0 - compensator;
        }
    }
}

extern "C" void kernel_launch(void* const* d_in, const int* in_sizes, int n_in,
                              void* d_out, int out_size) {
    const float* event_times = (const float*)d_in[0];
    const float* input_mask  = (const float*)d_in[1];
    const float* t0          = (const float*)d_in[2];
    const float* t1          = (const float*)d_in[3];
    const float* mu          = (const float*)d_in[4];
    const float* alpha       = (const float*)d_in[5];
    const float* beta        = (const float*)d_in[6];
    float* out = (float*)d_out;

    const int B = in_sizes[2];      // t0 has B elements
    const int N = in_sizes[0] / B;  // 4096

    hawkes_kernel<<<B, NT>>>(event_times, input_mask, t0, t1,
                             mu, alpha, beta, out, N);
}